// round 16
// baseline (speedup 1.0000x reference)
#include <cuda_runtime.h>
#include <cstdint>

#define NTOK   65536
#define DIMC   256
#define NCODE  1024
#define HWSZ   4096
#define ZSZ    16777216
#define OFF_ZQ      1
#define OFF_PERP    16777217
#define OFF_MINENC  16777218ULL
#define OFF_IDX     83886082ULL

#define TOKT 64

// smem byte offsets (dynamic): total 100 KB
#define O_AS    0          // [256 k][64 tok] f32 = 65536
#define O_BS    65536      // 2 x [16 k][256 code] f32 = 32768
#define O_EN    98304      // 1024 f32 = 4096
#define SMEM_BYTES 102400

// ---------------- scratch ----------------
__device__ float  g_et[DIMC * NCODE];     // [c][k]: embed transposed (K-major)
__device__ float  g_en[NCODE];
__device__ float  g_zn[NTOK];
__device__ int    g_idx[NTOK];
__device__ int    g_hist[NCODE];
__device__ double g_loss;

#define CPA16(dst, src) \
    asm volatile("cp.async.cg.shared.global [%0], [%1], 16;" :: "r"(dst), "l"(src))
#define CPA_COMMIT() asm volatile("cp.async.commit_group;")
#define CPA_WAIT(n)  asm volatile("cp.async.wait_group %0;" :: "n"(n))

// ---------------- k_argmin: direct fp32 FFMA GEMM + argmin ----------------
// 128 threads, 4 warps; each warp owns 16 tokens (M16), each lane 8 codes
// per 256-code tile (codes tx*4 and 128+tx*4). K=256 A tile resident;
// B streamed in 16-k-row chunks (16KB), double-buffered cp.async.
__global__ void __launch_bounds__(128, 2) k_argmin(const float* __restrict__ z) {
    extern __shared__ float sm[];
    float* As = sm;                      // As[k][tok], row 64 floats
    float* Bs = sm + (O_BS >> 2);        // Bs[buf][k][code], row 256 floats
    float* EN = sm + (O_EN >> 2);

    const uint32_t bs_s = (uint32_t)__cvta_generic_to_shared(Bs);

    int tid = threadIdx.x;
    int tx  = tid & 31;
    int wp  = tid >> 5;                  // warp id: tokens wp*16..+15
    int n0  = blockIdx.x * TOKT;
    int b   = n0 >> 12, hw0 = n0 & 4095;
    const float* zb = z + (size_t)b * (DIMC * HWSZ) + hw0;

    // ---- prefetch B chunk 0: 16 rows x 1KB = 1024 x 16B ----
    {
        const char* src = (const char*)g_et;
#pragma unroll
        for (int j = 0; j < 8; j++) {
            int u = tid + j * 128;
            int k = u >> 6, c16 = u & 63;
            CPA16(bs_s + (uint32_t)(k * 1024 + c16 * 16),
                  src + (size_t)k * 4096 + c16 * 16);
        }
        CPA_COMMIT();
    }

    // ---- load A tile: As[k][tok] for all 256 dims (coalesced over tok) ----
#pragma unroll
    for (int j = 0; j < 32; j++) {
        int u = tid + j * 128;                   // 4096 float4
        int c = u >> 4, t4 = u & 15;
        float4 v = *(const float4*)(zb + (size_t)c * HWSZ + t4 * 4);
        *(float4*)(As + c * 64 + t4 * 4) = v;
    }
    for (int i = tid; i < NCODE; i += 128) EN[i] = g_en[i];

    // per-thread state: 16 tokens x 8 codes
    float zn[16];
#pragma unroll
    for (int i = 0; i < 16; i++) zn[i] = g_zn[n0 + wp * 16 + i];
    float bv[16];
    int   bi[16];
#pragma unroll
    for (int i = 0; i < 16; i++) { bv[i] = 3.4e38f; bi[i] = 0; }

    CPA_WAIT(0);
    __syncthreads();

    float acc[16][8];

    for (int m = 0; m < 64; m++) {               // m = ct*16 + kc
        int ct = m >> 4, kc = m & 15, buf = m & 1;

        // prefetch next B chunk (16 rows x 1KB)
        if (m < 63) {
            int nct = (m + 1) >> 4, nkc = (m + 1) & 15;
            const char* src = (const char*)g_et
                            + (size_t)nkc * 16 * 4096 + (size_t)nct * 1024;
            uint32_t dst = bs_s + (uint32_t)((1 - buf) * 16384);
#pragma unroll
            for (int j = 0; j < 8; j++) {
                int u = tid + j * 128;
                int k = u >> 6, c16 = u & 63;
                CPA16(dst + (uint32_t)(k * 1024 + c16 * 16),
                      src + (size_t)k * 4096 + c16 * 16);
            }
            CPA_COMMIT();
        }

        if (kc == 0) {
#pragma unroll
            for (int i = 0; i < 16; i++)
#pragma unroll
                for (int j = 0; j < 8; j++) acc[i][j] = 0.0f;
        }

        // ---- compute: 16 k-steps, 128 FFMA each ----
        const float* ap = As + kc * 16 * 64 + wp * 16;
        const float* bp = Bs + buf * 4096 + tx * 4;
#pragma unroll 2
        for (int k = 0; k < 16; k++) {
            float a[16], bb[8];
            *(float4*)a        = *(const float4*)(ap + k * 64);        // broadcast
            *(float4*)(a + 4)  = *(const float4*)(ap + k * 64 + 4);
            *(float4*)(a + 8)  = *(const float4*)(ap + k * 64 + 8);
            *(float4*)(a + 12) = *(const float4*)(ap + k * 64 + 12);
            *(float4*)bb       = *(const float4*)(bp + k * 256);        // codes tx*4..+3
            *(float4*)(bb + 4) = *(const float4*)(bp + k * 256 + 128);  // codes 128+tx*4..+3
#pragma unroll
            for (int i = 0; i < 16; i++)
#pragma unroll
                for (int j = 0; j < 8; j++)
                    acc[i][j] = fmaf(a[i], bb[j], acc[i][j]);
        }

        // ---- epilogue at end of each code tile ----
        if (kc == 15) {
#pragma unroll
            for (int j = 0; j < 8; j++) {
                int code = ct * 256 + (j >> 2) * 128 + tx * 4 + (j & 3);
                float enj = EN[code];
#pragma unroll
                for (int i = 0; i < 16; i++) {
                    float v = (zn[i] + enj) - 2.0f * acc[i][j];
                    if (v < bv[i]) { bv[i] = v; bi[i] = code; }
                }
            }
        }

        if (m < 63) { CPA_WAIT(1); }
        __syncthreads();
    }

    // ---- warp-level argmin across tx lanes (first-index tie-break) ----
#pragma unroll
    for (int i = 0; i < 16; i++) {
        float v = bv[i];
        int   ix = bi[i];
#pragma unroll
        for (int o = 16; o; o >>= 1) {
            float ov = __shfl_xor_sync(0xffffffffu, v, o);
            int   oi = __shfl_xor_sync(0xffffffffu, ix, o);
            if (ov < v || (ov == v && oi < ix)) { v = ov; ix = oi; }
        }
        if (tx == 0) g_idx[n0 + wp * 16 + i] = ix;
    }
}

// ---------------- |z_n|^2 ----------------
__global__ void k_znorm(const float* __restrict__ z) {
    int b  = blockIdx.x >> 4;
    int hw = ((blockIdx.x & 15) << 8) + threadIdx.x;
    const float* p = z + (size_t)b * DIMC * HWSZ + hw;
    float s = 0.0f;
#pragma unroll 8
    for (int c = 0; c < DIMC; c++) {
        float v = p[(size_t)c * HWSZ];
        s = fmaf(v, v, s);
    }
    g_zn[b * HWSZ + hw] = s;
}

// ---------------- embed prep: transpose + |e|^2 + zero accum ----------------
__global__ void k_prep(const float* __restrict__ e) {
    int k = blockIdx.x;
    int t = threadIdx.x;                       // 64 threads, 4 dims each
    float4 v = ((const float4*)(e + (size_t)k * DIMC))[t];
    int c = t * 4;
    g_et[(c + 0) * NCODE + k] = v.x;
    g_et[(c + 1) * NCODE + k] = v.y;
    g_et[(c + 2) * NCODE + k] = v.z;
    g_et[(c + 3) * NCODE + k] = v.w;
    float s = v.x * v.x + v.y * v.y + v.z * v.z + v.w * v.w;
#pragma unroll
    for (int o = 16; o; o >>= 1) s += __shfl_down_sync(0xffffffffu, s, o);
    __shared__ float sh[2];
    if ((t & 31) == 0) sh[t >> 5] = s;
    __syncthreads();
    if (t == 0) {
        g_en[k]   = sh[0] + sh[1];
        g_hist[k] = 0;
        if (k == 0) g_loss = 0.0;
    }
}

// ---------------- z_q gather + loss + balanced one-hot/idx/hist ----------------
__global__ void k_epi(const float* __restrict__ z, float* __restrict__ out) {
    int i4  = blockIdx.x * 256 + threadIdx.x;      // over ZSZ/4
    int hw4 = i4 & 1023;
    int c   = (i4 >> 10) & 255;
    int b   = i4 >> 18;
    int4 kk = *(const int4*)(g_idx + (b << 12) + (hw4 << 2));
    float4 zv = ((const float4*)z)[i4];
    const float* row = g_et + c * NCODE;
    float dx = __ldg(&row[kk.x]) - zv.x;
    float dy = __ldg(&row[kk.y]) - zv.y;
    float dz = __ldg(&row[kk.z]) - zv.z;
    float dw = __ldg(&row[kk.w]) - zv.w;
    size_t o = OFF_ZQ + (size_t)i4 * 4;
    out[o + 0] = zv.x + dx;
    out[o + 1] = zv.y + dy;
    out[o + 2] = zv.z + dz;
    out[o + 3] = zv.w + dw;

    // balanced scatter: every block handles its own 4 tokens (threads 0..3)
    if (threadIdx.x < 4) {
        int n = blockIdx.x * 4 + threadIdx.x;
        int k = g_idx[n];
        out[OFF_MINENC + (size_t)n * NCODE + k] = 1.0f;
        out[OFF_IDX + n] = (float)k;
        atomicAdd(&g_hist[k], 1);
    }

    float s = dx * dx + dy * dy + dz * dz + dw * dw;
#pragma unroll
    for (int of = 16; of; of >>= 1) s += __shfl_down_sync(0xffffffffu, s, of);
    __shared__ float red[8];
    int t = threadIdx.x;
    if ((t & 31) == 0) red[t >> 5] = s;
    __syncthreads();
    if (t < 8) {
        float w = red[t];
#pragma unroll
        for (int of = 4; of; of >>= 1) w += __shfl_down_sync(0x000000ffu, w, of);
        if (t == 0) atomicAdd(&g_loss, (double)w);
    }
}

// ---------------- finalize ----------------
__global__ void k_fin(float* __restrict__ out) {
    int t = threadIdx.x;
    float em = (float)g_hist[t] * (1.0f / 65536.0f);
    float v = em * logf(em + 1e-10f);
    __shared__ float sh[32];
#pragma unroll
    for (int o = 16; o; o >>= 1) v += __shfl_down_sync(0xffffffffu, v, o);
    if ((t & 31) == 0) sh[t >> 5] = v;
    __syncthreads();
    if (t < 32) {
        float w = sh[t];
#pragma unroll
        for (int o = 16; o; o >>= 1) w += __shfl_down_sync(0xffffffffu, w, o);
        if (t == 0) {
            out[OFF_PERP] = expf(-w);
            out[0] = (float)(g_loss * (1.25 / 16777216.0));
        }
    }
}

// ---------------- launch ----------------
extern "C" void kernel_launch(void* const* d_in, const int* in_sizes, int n_in,
                              void* d_out, int out_size) {
    const float* z = (const float*)d_in[0];
    const float* e = (const float*)d_in[1];
    float* out = (float*)d_out;
    (void)in_sizes; (void)n_in; (void)out_size;

    static cudaStream_t s_side = 0;
    static cudaEvent_t  ev_fork = 0, ev_zn = 0, ev_join = 0;
    static int init_done = 0;
    if (!init_done) {
        cudaFuncSetAttribute(k_argmin, cudaFuncAttributeMaxDynamicSharedMemorySize, SMEM_BYTES);
        cudaStreamCreateWithFlags(&s_side, cudaStreamNonBlocking);
        cudaEventCreateWithFlags(&ev_fork, cudaEventDisableTiming);
        cudaEventCreateWithFlags(&ev_zn,   cudaEventDisableTiming);
        cudaEventCreateWithFlags(&ev_join, cudaEventDisableTiming);
        init_done = 1;
    }

    // fork: znorm + memset on side stream, concurrent with prep/argmin
    cudaEventRecord(ev_fork, 0);
    cudaStreamWaitEvent(s_side, ev_fork, 0);
    k_znorm <<<256, 256, 0, s_side>>>(z);
    cudaEventRecord(ev_zn, s_side);
    cudaMemsetAsync(out + OFF_MINENC, 0, 268435456ULL, s_side);
    cudaEventRecord(ev_join, s_side);

    k_prep  <<<NCODE, 64>>>(e);
    cudaStreamWaitEvent(0, ev_zn, 0);     // argmin reads g_zn
    k_argmin<<<NTOK / TOKT, 128, SMEM_BYTES>>>(z);

    // join: k_epi writes into the memset region
    cudaStreamWaitEvent(0, ev_join, 0);
    k_epi   <<<ZSZ / 1024, 256>>>(z, out);
    k_fin   <<<1, 1024>>>(out);
}

// round 17
// speedup vs baseline: 1.0464x; 1.0464x over previous
#include <cuda_runtime.h>
#include <cstdint>

#define NTOK   65536
#define DIMC   256
#define NCODE  1024
#define HWSZ   4096
#define ZSZ    16777216
#define OFF_ZQ      1
#define OFF_PERP    16777217
#define OFF_MINENC  16777218ULL
#define OFF_IDX     83886082ULL

#define TOKT 64

// smem byte offsets (dynamic): total 100 KB
#define O_AS    0          // [256 k][64 tok] f32 = 65536
#define O_BS    65536      // 2 x [16 k][256 code] f32 = 32768
#define O_EN    98304      // 1024 f32 = 4096
#define SMEM_BYTES 102400

// ---------------- scratch ----------------
__device__ float  g_et[DIMC * NCODE];     // [c][k]: embed transposed (K-major)
__device__ float  g_en[NCODE];
__device__ float  g_zn[NTOK];
__device__ int    g_idx[NTOK];
__device__ int    g_hist[NCODE];
__device__ double g_loss;

#define CPA16(dst, src) \
    asm volatile("cp.async.cg.shared.global [%0], [%1], 16;" :: "r"(dst), "l"(src))
#define CPA_COMMIT() asm volatile("cp.async.commit_group;")
#define CPA_WAIT(n)  asm volatile("cp.async.wait_group %0;" :: "n"(n))

// ---------------- k_argmin: direct fp32 FFMA GEMM + argmin ----------------
// 128 threads, 4 warps; each warp owns 16 tokens (M16), each lane 8 codes
// per 256-code tile (codes tx*4 and 128+tx*4). K=256 A tile resident;
// B streamed in 16-k-row chunks (16KB), double-buffered cp.async.
__global__ void __launch_bounds__(128, 2) k_argmin(const float* __restrict__ z) {
    extern __shared__ float sm[];
    float* As = sm;                      // As[k][tok], row 64 floats
    float* Bs = sm + (O_BS >> 2);        // Bs[buf][k][code], row 256 floats
    float* EN = sm + (O_EN >> 2);

    const uint32_t bs_s = (uint32_t)__cvta_generic_to_shared(Bs);

    int tid = threadIdx.x;
    int tx  = tid & 31;
    int wp  = tid >> 5;                  // warp id: tokens wp*16..+15
    int n0  = blockIdx.x * TOKT;
    int b   = n0 >> 12, hw0 = n0 & 4095;
    const float* zb = z + (size_t)b * (DIMC * HWSZ) + hw0;

    // ---- prefetch B chunk 0: 16 rows x 1KB = 1024 x 16B ----
    {
        const char* src = (const char*)g_et;
#pragma unroll
        for (int j = 0; j < 8; j++) {
            int u = tid + j * 128;
            int k = u >> 6, c16 = u & 63;
            CPA16(bs_s + (uint32_t)(k * 1024 + c16 * 16),
                  src + (size_t)k * 4096 + c16 * 16);
        }
        CPA_COMMIT();
    }

    // ---- load A tile: As[k][tok] for all 256 dims (coalesced over tok) ----
#pragma unroll
    for (int j = 0; j < 32; j++) {
        int u = tid + j * 128;                   // 4096 float4
        int c = u >> 4, t4 = u & 15;
        float4 v = *(const float4*)(zb + (size_t)c * HWSZ + t4 * 4);
        *(float4*)(As + c * 64 + t4 * 4) = v;
    }
    for (int i = tid; i < NCODE; i += 128) EN[i] = g_en[i];

    // per-thread state: 16 tokens x 8 codes
    float zn[16];
#pragma unroll
    for (int i = 0; i < 16; i++) zn[i] = g_zn[n0 + wp * 16 + i];
    float bv[16];
    int   bi[16];
#pragma unroll
    for (int i = 0; i < 16; i++) { bv[i] = 3.4e38f; bi[i] = 0; }

    CPA_WAIT(0);
    __syncthreads();

    float acc[16][8];

    for (int m = 0; m < 64; m++) {               // m = ct*16 + kc
        int ct = m >> 4, kc = m & 15, buf = m & 1;

        // prefetch next B chunk (16 rows x 1KB)
        if (m < 63) {
            int nct = (m + 1) >> 4, nkc = (m + 1) & 15;
            const char* src = (const char*)g_et
                            + (size_t)nkc * 16 * 4096 + (size_t)nct * 1024;
            uint32_t dst = bs_s + (uint32_t)((1 - buf) * 16384);
#pragma unroll
            for (int j = 0; j < 8; j++) {
                int u = tid + j * 128;
                int k = u >> 6, c16 = u & 63;
                CPA16(dst + (uint32_t)(k * 1024 + c16 * 16),
                      src + (size_t)k * 4096 + c16 * 16);
            }
            CPA_COMMIT();
        }

        if (kc == 0) {
#pragma unroll
            for (int i = 0; i < 16; i++)
#pragma unroll
                for (int j = 0; j < 8; j++) acc[i][j] = 0.0f;
        }

        // ---- compute: 16 k-steps, 128 FFMA each ----
        const float* ap = As + kc * 16 * 64 + wp * 16;
        const float* bp = Bs + buf * 4096 + tx * 4;
#pragma unroll 2
        for (int k = 0; k < 16; k++) {
            float a[16], bb[8];
            *(float4*)a        = *(const float4*)(ap + k * 64);        // broadcast
            *(float4*)(a + 4)  = *(const float4*)(ap + k * 64 + 4);
            *(float4*)(a + 8)  = *(const float4*)(ap + k * 64 + 8);
            *(float4*)(a + 12) = *(const float4*)(ap + k * 64 + 12);
            *(float4*)bb       = *(const float4*)(bp + k * 256);        // codes tx*4..+3
            *(float4*)(bb + 4) = *(const float4*)(bp + k * 256 + 128);  // codes 128+tx*4..+3
#pragma unroll
            for (int i = 0; i < 16; i++)
#pragma unroll
                for (int j = 0; j < 8; j++)
                    acc[i][j] = fmaf(a[i], bb[j], acc[i][j]);
        }

        // ---- epilogue at end of each code tile ----
        if (kc == 15) {
#pragma unroll
            for (int j = 0; j < 8; j++) {
                int code = ct * 256 + (j >> 2) * 128 + tx * 4 + (j & 3);
                float enj = EN[code];
#pragma unroll
                for (int i = 0; i < 16; i++) {
                    float v = (zn[i] + enj) - 2.0f * acc[i][j];
                    if (v < bv[i]) { bv[i] = v; bi[i] = code; }
                }
            }
        }

        if (m < 63) { CPA_WAIT(1); }
        __syncthreads();
    }

    // ---- warp-level argmin across tx lanes (first-index tie-break) ----
#pragma unroll
    for (int i = 0; i < 16; i++) {
        float v = bv[i];
        int   ix = bi[i];
#pragma unroll
        for (int o = 16; o; o >>= 1) {
            float ov = __shfl_xor_sync(0xffffffffu, v, o);
            int   oi = __shfl_xor_sync(0xffffffffu, ix, o);
            if (ov < v || (ov == v && oi < ix)) { v = ov; ix = oi; }
        }
        if (tx == 0) g_idx[n0 + wp * 16 + i] = ix;
    }
}

// ---------------- |z_n|^2 ----------------
__global__ void k_znorm(const float* __restrict__ z) {
    int b  = blockIdx.x >> 4;
    int hw = ((blockIdx.x & 15) << 8) + threadIdx.x;
    const float* p = z + (size_t)b * DIMC * HWSZ + hw;
    float s = 0.0f;
#pragma unroll 8
    for (int c = 0; c < DIMC; c++) {
        float v = p[(size_t)c * HWSZ];
        s = fmaf(v, v, s);
    }
    g_zn[b * HWSZ + hw] = s;
}

// ---------------- embed prep: transpose + |e|^2 + zero accum ----------------
__global__ void k_prep(const float* __restrict__ e) {
    int k = blockIdx.x;
    int t = threadIdx.x;                       // 64 threads, 4 dims each
    float4 v = ((const float4*)(e + (size_t)k * DIMC))[t];
    int c = t * 4;
    g_et[(c + 0) * NCODE + k] = v.x;
    g_et[(c + 1) * NCODE + k] = v.y;
    g_et[(c + 2) * NCODE + k] = v.z;
    g_et[(c + 3) * NCODE + k] = v.w;
    float s = v.x * v.x + v.y * v.y + v.z * v.z + v.w * v.w;
#pragma unroll
    for (int o = 16; o; o >>= 1) s += __shfl_down_sync(0xffffffffu, s, o);
    __shared__ float sh[2];
    if ((t & 31) == 0) sh[t >> 5] = s;
    __syncthreads();
    if (t == 0) {
        g_en[k]   = sh[0] + sh[1];
        g_hist[k] = 0;
        if (k == 0) g_loss = 0.0;
    }
}

// ---------------- z_q gather + loss + fused one-hot/idx/hist ----------------
__global__ void k_epi(const float* __restrict__ z, float* __restrict__ out) {
    int i4  = blockIdx.x * 256 + threadIdx.x;      // over ZSZ/4
    int hw4 = i4 & 1023;
    int c   = (i4 >> 10) & 255;
    int b   = i4 >> 18;
    int4 kk = *(const int4*)(g_idx + (b << 12) + (hw4 << 2));
    float4 zv = ((const float4*)z)[i4];
    const float* row = g_et + c * NCODE;
    float dx = __ldg(&row[kk.x]) - zv.x;
    float dy = __ldg(&row[kk.y]) - zv.y;
    float dz = __ldg(&row[kk.z]) - zv.z;
    float dw = __ldg(&row[kk.w]) - zv.w;
    size_t o = OFF_ZQ + (size_t)i4 * 4;
    out[o + 0] = zv.x + dx;
    out[o + 1] = zv.y + dy;
    out[o + 2] = zv.z + dz;
    out[o + 3] = zv.w + dw;

    // fused scatter work: one thread slice (c==0) handles its 4 tokens
    if (c == 0) {
        int n = (b << 12) + (hw4 << 2);
        out[OFF_MINENC + (size_t)(n + 0) * NCODE + kk.x] = 1.0f;
        out[OFF_MINENC + (size_t)(n + 1) * NCODE + kk.y] = 1.0f;
        out[OFF_MINENC + (size_t)(n + 2) * NCODE + kk.z] = 1.0f;
        out[OFF_MINENC + (size_t)(n + 3) * NCODE + kk.w] = 1.0f;
        // OFF_IDX is 8-byte aligned only: use float2 stores, not float4
        float* ip = out + OFF_IDX + n;
        *(float2*)(ip)     = make_float2((float)kk.x, (float)kk.y);
        *(float2*)(ip + 2) = make_float2((float)kk.z, (float)kk.w);
        atomicAdd(&g_hist[kk.x], 1);
        atomicAdd(&g_hist[kk.y], 1);
        atomicAdd(&g_hist[kk.z], 1);
        atomicAdd(&g_hist[kk.w], 1);
    }

    float s = dx * dx + dy * dy + dz * dz + dw * dw;
#pragma unroll
    for (int of = 16; of; of >>= 1) s += __shfl_down_sync(0xffffffffu, s, of);
    __shared__ float red[8];
    int t = threadIdx.x;
    if ((t & 31) == 0) red[t >> 5] = s;
    __syncthreads();
    if (t < 8) {
        float w = red[t];
#pragma unroll
        for (int of = 4; of; of >>= 1) w += __shfl_down_sync(0x000000ffu, w, of);
        if (t == 0) atomicAdd(&g_loss, (double)w);
    }
}

// ---------------- finalize ----------------
__global__ void k_fin(float* __restrict__ out) {
    int t = threadIdx.x;
    float em = (float)g_hist[t] * (1.0f / 65536.0f);
    float v = em * logf(em + 1e-10f);
    __shared__ float sh[32];
#pragma unroll
    for (int o = 16; o; o >>= 1) v += __shfl_down_sync(0xffffffffu, v, o);
    if ((t & 31) == 0) sh[t >> 5] = v;
    __syncthreads();
    if (t < 32) {
        float w = sh[t];
#pragma unroll
        for (int o = 16; o; o >>= 1) w += __shfl_down_sync(0xffffffffu, w, o);
        if (t == 0) {
            out[OFF_PERP] = expf(-w);
            out[0] = (float)(g_loss * (1.25 / 16777216.0));
        }
    }
}

// ---------------- launch ----------------
extern "C" void kernel_launch(void* const* d_in, const int* in_sizes, int n_in,
                              void* d_out, int out_size) {
    const float* z = (const float*)d_in[0];
    const float* e = (const float*)d_in[1];
    float* out = (float*)d_out;
    (void)in_sizes; (void)n_in; (void)out_size;

    static cudaStream_t s_side = 0;
    static cudaEvent_t  ev_fork = 0, ev_join = 0;
    static int init_done = 0;
    if (!init_done) {
        cudaFuncSetAttribute(k_argmin, cudaFuncAttributeMaxDynamicSharedMemorySize, SMEM_BYTES);
        cudaStreamCreateWithFlags(&s_side, cudaStreamNonBlocking);
        cudaEventCreateWithFlags(&ev_fork, cudaEventDisableTiming);
        cudaEventCreateWithFlags(&ev_join, cudaEventDisableTiming);
        init_done = 1;
    }

    // fork: memset one-hot region concurrently with prep/znorm/argmin
    cudaEventRecord(ev_fork, 0);
    cudaStreamWaitEvent(s_side, ev_fork, 0);
    cudaMemsetAsync(out + OFF_MINENC, 0, 268435456ULL, s_side);
    cudaEventRecord(ev_join, s_side);

    k_prep  <<<NCODE, 64>>>(e);
    k_znorm <<<256, 256>>>(z);
    k_argmin<<<NTOK / TOKT, 128, SMEM_BYTES>>>(z);

    // join: k_epi writes into the memset region
    cudaStreamWaitEvent(0, ev_join, 0);
    k_epi   <<<ZSZ / 1024, 256>>>(z, out);
    k_fin   <<<1, 1024>>>(out);
}